// round 1
// baseline (speedup 1.0000x reference)
#include <cuda_runtime.h>
#include <math.h>

// Problem constants
#define NB 2
#define NS 512
#define ND 256
#define NH 8
#define NA 32
#define NBS (NB*NS)          // 1024
#define B_CONSTF 0.9f
#define EPSF 1e-10f
#define SCALEF 0.0625f       // 1/sqrt(256)

// ---------------- device scratch (no allocations allowed) ----------------
__device__ float g_q [NBS*ND];        // 1 MB
__device__ float g_kv[NBS*2*ND];      // 2 MB  (k: cols 0..255, v: cols 256..511)
__device__ float g_vz[NBS*ND];        // 1 MB  v_norm^p
__device__ float g_e [NBS*ND];        // 1 MB  un-normalized power-mean
__device__ float g_vmin   [NB*ND];
__device__ float g_nscale [NB*ND];    // (1-B)/(range+eps)
__device__ float g_unscale[NB*ND];    // (range+eps)/(1-B)
__device__ float g_p   [ND];
__device__ float g_invp[ND];

// ---------------- generic C[M,N] = A[M,K] @ B[N,K]^T ----------------
// 64x64 block tile, BK=16, 256 threads, 4x4 per thread
__global__ void gemm_nt_kernel(const float* __restrict__ A,
                               const float* __restrict__ Bm,
                               float* __restrict__ C,
                               int M, int N, int K) {
    __shared__ float As[64][17];
    __shared__ float Bs[64][17];
    const int tid = threadIdx.x;
    const int tx  = tid & 15;
    const int ty  = tid >> 4;
    const int bm  = blockIdx.y * 64;
    const int bn  = blockIdx.x * 64;

    float acc[4][4];
    #pragma unroll
    for (int i = 0; i < 4; i++)
        #pragma unroll
        for (int j = 0; j < 4; j++) acc[i][j] = 0.f;

    const int lm = tid >> 2;         // 0..63
    const int lk = (tid & 3) << 2;   // 0,4,8,12

    for (int k0 = 0; k0 < K; k0 += 16) {
        float4 a4 = *(const float4*)&A [(bm + lm) * K + k0 + lk];
        As[lm][lk+0] = a4.x; As[lm][lk+1] = a4.y;
        As[lm][lk+2] = a4.z; As[lm][lk+3] = a4.w;
        float4 b4 = *(const float4*)&Bm[(bn + lm) * K + k0 + lk];
        Bs[lm][lk+0] = b4.x; Bs[lm][lk+1] = b4.y;
        Bs[lm][lk+2] = b4.z; Bs[lm][lk+3] = b4.w;
        __syncthreads();
        #pragma unroll
        for (int kk = 0; kk < 16; kk++) {
            float ra[4], rb[4];
            #pragma unroll
            for (int i = 0; i < 4; i++) ra[i] = As[ty*4 + i][kk];
            #pragma unroll
            for (int j = 0; j < 4; j++) rb[j] = Bs[tx*4 + j][kk];
            #pragma unroll
            for (int i = 0; i < 4; i++)
                #pragma unroll
                for (int j = 0; j < 4; j++)
                    acc[i][j] += ra[i] * rb[j];
        }
        __syncthreads();
    }
    #pragma unroll
    for (int i = 0; i < 4; i++)
        #pragma unroll
        for (int j = 0; j < 4; j++)
            C[(bm + ty*4 + i) * N + bn + tx*4 + j] = acc[i][j];
}

// ---------------- per-(b,d) min/max over S + p / invp ----------------
// grid = NB blocks, 1024 threads: d = tid&255, S-slice = tid>>8 (4 slices x 128)
__global__ void vstats_kernel(const float* __restrict__ p_param) {
    __shared__ float smn[4][256];
    __shared__ float smx[4][256];
    const int b  = blockIdx.x;
    const int d  = threadIdx.x & 255;
    const int sl = threadIdx.x >> 8;

    float vmn = 1e30f, vmx = -1e30f;
    const float* base = g_kv + (size_t)(b * NS + sl * 128) * (2 * ND) + ND + d;
    #pragma unroll 8
    for (int s = 0; s < 128; s++) {
        float v = base[s * (2 * ND)];
        vmn = fminf(vmn, v);
        vmx = fmaxf(vmx, v);
    }
    smn[sl][d] = vmn;
    smx[sl][d] = vmx;
    __syncthreads();
    if (sl == 0) {
        vmn = fminf(fminf(smn[0][d], smn[1][d]), fminf(smn[2][d], smn[3][d]));
        vmx = fmaxf(fmaxf(smx[0][d], smx[1][d]), fmaxf(smx[2][d], smx[3][d]));
        float range = vmx - vmn + EPSF;
        g_vmin   [b*ND + d] = vmn;
        g_nscale [b*ND + d] = (1.0f - B_CONSTF) / range;
        g_unscale[b*ND + d] = range / (1.0f - B_CONSTF);
        if (b == 0) {
            float pp = p_param[d];
            float p  = 50000.0f * tanhf(0.005f * pp) + 1.0f;
            if (p == 0.0f) p = 1e-4f;   // reference: p += (p==0)*P_MIN
            g_p   [d] = p;
            g_invp[d] = 1.0f / p;
        }
    }
}

// ---------------- vz = v_norm^p, elementwise ----------------
__global__ void vz_kernel() {
    int idx = blockIdx.x * blockDim.x + threadIdx.x;
    if (idx >= NBS * ND) return;
    int d  = idx & (ND - 1);
    int bs = idx >> 8;
    int b  = bs >> 9;
    float v  = g_kv[(size_t)bs * (2 * ND) + ND + d];
    float vn = (v - g_vmin[b*ND + d]) * g_nscale[b*ND + d] + B_CONSTF;
    g_vz[idx] = __expf(g_p[d] * __logf(vn));
}

// ---------------- attention: power-mean softmax ----------------
// grid = 128 blocks: b(1b) x h(3b) x qtile(3b); 256 threads = 64 queries x 4 key-slices
// smem: Ks[512][32] + Vs[512][32] = 128 KB (reused as merge buffer afterwards)
__global__ void attn_kernel() {
    extern __shared__ float smem[];
    float* Ks = smem;
    float* Vs = smem + NS * NA;

    const int bz = blockIdx.x;
    const int b  = bz >> 6;
    const int h  = (bz >> 3) & 7;
    const int qt = bz & 7;
    const int tid = threadIdx.x;

    // stage full head K and V^p tiles
    for (int e = tid; e < NS * 8; e += 256) {
        int s = e >> 3;
        int c = (e & 7) << 2;
        *(float4*)&Ks[s*NA + c] = *(const float4*)&g_kv[(size_t)(b*NS + s)*(2*ND) + h*NA + c];
        *(float4*)&Vs[s*NA + c] = *(const float4*)&g_vz[(size_t)(b*NS + s)*ND + h*NA + c];
    }
    __syncthreads();

    const int ql    = tid & 63;
    const int slice = tid >> 6;
    const int qg    = qt * 64 + ql;

    float qv[NA];
    {
        const float* qptr = &g_q[(size_t)(b*NS + qg)*ND + h*NA];
        #pragma unroll
        for (int i = 0; i < 8; i++) {
            float4 t = *(const float4*)&qptr[i*4];
            qv[4*i] = t.x; qv[4*i+1] = t.y; qv[4*i+2] = t.z; qv[4*i+3] = t.w;
        }
    }

    float acc[NA];
    #pragma unroll
    for (int a = 0; a < NA; a++) acc[a] = 0.f;
    float l = 0.f;

    const int j0 = slice * 128;
    for (int j = j0; j < j0 + 128; j++) {
        const float* kj = &Ks[j*NA];
        float s0 = 0.f, s1 = 0.f, s2 = 0.f, s3 = 0.f;
        #pragma unroll
        for (int i = 0; i < 8; i++) {
            float4 kq = *(const float4*)&kj[4*i];   // warp-broadcast LDS.128
            s0 += qv[4*i+0] * kq.x;
            s1 += qv[4*i+1] * kq.y;
            s2 += qv[4*i+2] * kq.z;
            s3 += qv[4*i+3] * kq.w;
        }
        float w = __expf(((s0 + s1) + (s2 + s3)) * SCALEF);
        l += w;
        const float* vj = &Vs[j*NA];
        #pragma unroll
        for (int i = 0; i < 8; i++) {
            float4 vq = *(const float4*)&vj[4*i];
            acc[4*i+0] += w * vq.x;
            acc[4*i+1] += w * vq.y;
            acc[4*i+2] += w * vq.z;
            acc[4*i+3] += w * vq.w;
        }
    }
    __syncthreads();   // Ks/Vs no longer needed

    // merge 4 slices: pure addition (no max subtraction anywhere)
    float* red = smem;                       // [4][64][33]
    float* my  = &red[(slice*64 + ql) * 33];
    my[0] = l;
    #pragma unroll
    for (int a = 0; a < NA; a++) my[1+a] = acc[a];
    __syncthreads();

    if (tid < 64) {
        const float* r0 = &red[(0*64 + tid) * 33];
        const float* r1 = &red[(1*64 + tid) * 33];
        const float* r2 = &red[(2*64 + tid) * 33];
        const float* r3 = &red[(3*64 + tid) * 33];
        float L    = (r0[0] + r1[0]) + (r2[0] + r3[0]);
        float invL = 1.0f / L;
        int   qq   = qt * 64 + tid;
        float* outp = &g_e[(size_t)(b*NS + qq)*ND + h*NA];
        #pragma unroll
        for (int a = 0; a < NA; a++) {
            float S  = ((r0[1+a] + r1[1+a]) + (r2[1+a] + r3[1+a])) * invL;
            int   d  = h*NA + a;
            float ev = __expf(__logf(S) * g_invp[d]);          // S^(1/p)
            outp[a]  = (ev - B_CONSTF) * g_unscale[b*ND + d] + g_vmin[b*ND + d];
        }
    }
}

// ---------------- launch ----------------
extern "C" void kernel_launch(void* const* d_in, const int* in_sizes, int n_in,
                              void* d_out, int out_size) {
    const float* context = (const float*)d_in[0];
    const float* W_Q     = (const float*)d_in[1];
    const float* W_KV    = (const float*)d_in[2];
    const float* W_out   = (const float*)d_in[3];
    const float* p_param = (const float*)d_in[4];
    float* out = (float*)d_out;

    float *pq, *pkv, *pe;
    cudaGetSymbolAddress((void**)&pq,  g_q);
    cudaGetSymbolAddress((void**)&pkv, g_kv);
    cudaGetSymbolAddress((void**)&pe,  g_e);

    // projections
    gemm_nt_kernel<<<dim3(4, 16), 256>>>(context, W_Q,  pq,  NBS, ND,     ND);
    gemm_nt_kernel<<<dim3(8, 16), 256>>>(context, W_KV, pkv, NBS, 2*ND,   ND);

    // v stats + p
    vstats_kernel<<<NB, 1024>>>(p_param);

    // vz = v_norm^p
    vz_kernel<<<(NBS*ND)/256, 256>>>();

    // attention (power-mean)
    cudaFuncSetAttribute(attn_kernel, cudaFuncAttributeMaxDynamicSharedMemorySize, 131072);
    attn_kernel<<<128, 256, 131072>>>();

    // output projection
    gemm_nt_kernel<<<dim3(4, 16), 256>>>(pe, W_out, out, NBS, ND, ND);
}